// round 4
// baseline (speedup 1.0000x reference)
#include <cuda_runtime.h>

#define NN   50000
#define EE   800000
#define INC  512
#define HID  256
#define OUTC 64
#define PHOPS 10

// ---------------- scratch (static device globals; no allocation) ----------------
__device__ float g_h0[(size_t)NN * HID];     // relu(x@W1+b1)
__device__ float g_hA[(size_t)NN * OUTC];    // ping
__device__ float g_hB[(size_t)NN * OUTC];    // pong
__device__ float g_hidden[(size_t)NN * OUTC];
__device__ int   g_counts[NN];
__device__ int   g_fill[NN];
__device__ int   g_colptr[NN + 1];
__device__ int   g_src[EE];
__device__ float g_w[EE];
__device__ float g_dinv[NN];
__device__ int   g_is64;                     // 1 if edge_index delivered as int64

// ---------------- dtype detection (deterministic: fixed input data) ----------------
__global__ void k_detect(const void* __restrict__ ei) {
    if (blockIdx.x == 0 && threadIdx.x == 0) {
        const long long* e64 = (const long long*)ei;
        int ok = 1;
#pragma unroll
        for (int i = 0; i < 16; i++) {
            long long v = e64[i];
            if (v < 0 || v >= NN) ok = 0;
        }
        g_is64 = ok;
    }
}

__device__ __forceinline__ void load_edge(const void* __restrict__ ei, int i,
                                          int& r, int& c) {
    if (g_is64) {
        r = (int)((const long long*)ei)[i];
        c = (int)((const long long*)ei)[EE + i];
    } else {
        r = ((const int*)ei)[i];
        c = ((const int*)ei)[EE + i];
    }
}

// ---------------- preprocessing ----------------
__global__ void k_zero() {
    int i = blockIdx.x * blockDim.x + threadIdx.x;
    if (i < NN) { g_counts[i] = 0; g_fill[i] = 0; }
}

__global__ void k_hist(const void* __restrict__ ei) {
    int i = blockIdx.x * blockDim.x + threadIdx.x;
    if (i < EE) {
        int r, c;
        load_edge(ei, i, r, c);
        if ((unsigned)c < NN) atomicAdd(&g_counts[c], 1);
    }
}

__global__ void k_dinv() {
    int i = blockIdx.x * blockDim.x + threadIdx.x;
    if (i < NN) g_dinv[i] = rsqrtf((float)(g_counts[i] + 1)); // +1 self loop
}

// single-block exclusive scan of g_counts -> g_colptr (50k elems, ~49 chunk iters)
__global__ void k_scan() {
    __shared__ int sdata[1024];
    int tid = threadIdx.x;
    int running = 0;
    for (int base = 0; base < NN; base += 1024) {
        __syncthreads();
        int v = (base + tid < NN) ? g_counts[base + tid] : 0;
        sdata[tid] = v;
        __syncthreads();
        for (int off = 1; off < 1024; off <<= 1) {
            int t = (tid >= off) ? sdata[tid - off] : 0;
            __syncthreads();
            sdata[tid] += t;
            __syncthreads();
        }
        if (base + tid < NN) g_colptr[base + tid] = running + sdata[tid] - v;
        running += sdata[1023];
    }
    if (tid == 0) g_colptr[NN] = running;
}

__global__ void k_scatter(const void* __restrict__ ei) {
    int i = blockIdx.x * blockDim.x + threadIdx.x;
    if (i < EE) {
        int r, c;
        load_edge(ei, i, r, c);
        if ((unsigned)r >= NN || (unsigned)c >= NN) return;
        int pos = g_colptr[c] + atomicAdd(&g_fill[c], 1);
        if ((unsigned)pos < EE) {
            g_src[pos] = r;
            g_w[pos]   = g_dinv[r] * g_dinv[c];
        }
    }
}

// ---------------- GEMM1: h0 = relu(X[NN,512] @ W1[512,256] + b1) ----------------
// BM=64, BN=64, BK=16, 256 threads, 4x4 per thread
__global__ void k_gemm1(const float* __restrict__ X, const float* __restrict__ W,
                        const float* __restrict__ b) {
    __shared__ float As[16][65];   // padded: conflict-light transposed stores
    __shared__ float Bs[16][64];
    int m0 = blockIdx.x * 64;
    int n0 = blockIdx.y * 64;
    int t  = threadIdx.x;
    int tm = (t >> 4) << 2;
    int tn = (t & 15) << 2;
    int arow = t >> 2, aseg = t & 3;   // A tile: 64 rows x 16 cols, one float4/thread
    int brow = t >> 4, bseg = t & 15;  // B tile: 16 rows x 64 cols, one float4/thread

    float acc[4][4];
#pragma unroll
    for (int i = 0; i < 4; i++)
#pragma unroll
        for (int j = 0; j < 4; j++) acc[i][j] = 0.f;

    for (int k0 = 0; k0 < INC; k0 += 16) {
        float4 av = make_float4(0.f, 0.f, 0.f, 0.f);
        int ar = m0 + arow;
        if (ar < NN) av = *(const float4*)&X[(size_t)ar * INC + k0 + aseg * 4];
        float4 bv = *(const float4*)&W[(size_t)(k0 + brow) * HID + n0 + bseg * 4];
        __syncthreads();
        As[aseg * 4 + 0][arow] = av.x;
        As[aseg * 4 + 1][arow] = av.y;
        As[aseg * 4 + 2][arow] = av.z;
        As[aseg * 4 + 3][arow] = av.w;
        *(float4*)&Bs[brow][bseg * 4] = bv;
        __syncthreads();
#pragma unroll
        for (int k = 0; k < 16; k++) {
            float a[4], bb[4];
#pragma unroll
            for (int i = 0; i < 4; i++) a[i] = As[k][tm + i];
#pragma unroll
            for (int j = 0; j < 4; j++) bb[j] = Bs[k][tn + j];
#pragma unroll
            for (int i = 0; i < 4; i++)
#pragma unroll
                for (int j = 0; j < 4; j++) acc[i][j] = fmaf(a[i], bb[j], acc[i][j]);
        }
    }
#pragma unroll
    for (int i = 0; i < 4; i++) {
        int m = m0 + tm + i;
        if (m < NN) {
#pragma unroll
            for (int j = 0; j < 4; j++) {
                float v = acc[i][j] + b[n0 + tn + j];
                g_h0[(size_t)m * HID + n0 + tn + j] = fmaxf(v, 0.f);
            }
        }
    }
}

// ---------------- GEMM2: hA = h0[NN,256] @ W2[256,64] + b2; hidden = coes[0]*hA ----
__global__ void k_gemm2(const float* __restrict__ W, const float* __restrict__ b,
                        const float* __restrict__ coes) {
    __shared__ float As[16][65];
    __shared__ float Bs[16][64];
    int m0 = blockIdx.x * 64;
    int t  = threadIdx.x;
    int tm = (t >> 4) << 2;
    int tn = (t & 15) << 2;
    int arow = t >> 2, aseg = t & 3;
    int brow = t >> 4, bseg = t & 15;

    float acc[4][4];
#pragma unroll
    for (int i = 0; i < 4; i++)
#pragma unroll
        for (int j = 0; j < 4; j++) acc[i][j] = 0.f;

    for (int k0 = 0; k0 < HID; k0 += 16) {
        float4 av = make_float4(0.f, 0.f, 0.f, 0.f);
        int ar = m0 + arow;
        if (ar < NN) av = *(const float4*)&g_h0[(size_t)ar * HID + k0 + aseg * 4];
        float4 bv = *(const float4*)&W[(size_t)(k0 + brow) * OUTC + bseg * 4];
        __syncthreads();
        As[aseg * 4 + 0][arow] = av.x;
        As[aseg * 4 + 1][arow] = av.y;
        As[aseg * 4 + 2][arow] = av.z;
        As[aseg * 4 + 3][arow] = av.w;
        *(float4*)&Bs[brow][bseg * 4] = bv;
        __syncthreads();
#pragma unroll
        for (int k = 0; k < 16; k++) {
            float a[4], bb[4];
#pragma unroll
            for (int i = 0; i < 4; i++) a[i] = As[k][tm + i];
#pragma unroll
            for (int j = 0; j < 4; j++) bb[j] = Bs[k][tn + j];
#pragma unroll
            for (int i = 0; i < 4; i++)
#pragma unroll
                for (int j = 0; j < 4; j++) acc[i][j] = fmaf(a[i], bb[j], acc[i][j]);
        }
    }
    float c0 = coes[0];
#pragma unroll
    for (int i = 0; i < 4; i++) {
        int m = m0 + tm + i;
        if (m < NN) {
#pragma unroll
            for (int j = 0; j < 4; j++) {
                float v = acc[i][j] + b[tn + j];
                size_t o = (size_t)m * OUTC + tn + j;
                g_hA[o]     = v;
                g_hidden[o] = c0 * v;
            }
        }
    }
}

// ---------------- SpMM hop: warp per node, 64 feats = 2/lane ----------------
__global__ void k_spmm(int parity, const float* __restrict__ coes, int p) {
    int gid  = blockIdx.x * blockDim.x + threadIdx.x;
    int node = gid >> 5;
    int lane = gid & 31;
    if (node >= NN) return;
    const float* __restrict__ hin  = parity ? g_hB : g_hA;
    float* __restrict__       hout = parity ? g_hA : g_hB;

    int beg = g_colptr[node], end = g_colptr[node + 1];
    float a0 = 0.f, a1 = 0.f;
    for (int e = beg; e < end; e++) {
        int   s = g_src[e];
        float w = g_w[e];
        const float* hr = hin + (size_t)s * OUTC;
        a0 = fmaf(w, hr[lane],      a0);
        a1 = fmaf(w, hr[lane + 32], a1);
    }
    // self loop
    float d = g_dinv[node];
    float wd = d * d;
    const float* hs = hin + (size_t)node * OUTC;
    a0 = fmaf(wd, hs[lane],      a0);
    a1 = fmaf(wd, hs[lane + 32], a1);

    size_t o = (size_t)node * OUTC;
    hout[o + lane]      = a0;
    hout[o + lane + 32] = a1;
    float c = coes[p];
    g_hidden[o + lane]      += c * a0;
    g_hidden[o + lane + 32] += c * a1;
}

// ---------------- log_softmax over 64 feats ----------------
__global__ void k_lsm(float* __restrict__ out) {
    int gid  = blockIdx.x * blockDim.x + threadIdx.x;
    int node = gid >> 5;
    int lane = gid & 31;
    if (node >= NN) return;
    size_t o = (size_t)node * OUTC;
    float v0 = g_hidden[o + lane];
    float v1 = g_hidden[o + lane + 32];
    float m = fmaxf(v0, v1);
#pragma unroll
    for (int off = 16; off; off >>= 1) m = fmaxf(m, __shfl_xor_sync(0xffffffffu, m, off));
    float s = expf(v0 - m) + expf(v1 - m);
#pragma unroll
    for (int off = 16; off; off >>= 1) s += __shfl_xor_sync(0xffffffffu, s, off);
    float l = m + logf(s);
    out[o + lane]      = v0 - l;
    out[o + lane + 32] = v1 - l;
}

// ---------------- launch ----------------
extern "C" void kernel_launch(void* const* d_in, const int* in_sizes, int n_in,
                              void* d_out, int out_size) {
    const float* x    = (const float*)d_in[0];
    const void*  ei   = d_in[1];                // int32 or int64: detected on device
    const float* W1   = (const float*)d_in[2];
    const float* b1   = (const float*)d_in[3];
    const float* W2   = (const float*)d_in[4];
    const float* b2   = (const float*)d_in[5];
    const float* coes = (const float*)d_in[6];
    (void)in_sizes; (void)n_in; (void)out_size;

    k_detect<<<1, 32>>>(ei);
    k_zero<<<(NN + 255) / 256, 256>>>();
    k_hist<<<(EE + 255) / 256, 256>>>(ei);
    k_dinv<<<(NN + 255) / 256, 256>>>();
    k_scan<<<1, 1024>>>();
    k_scatter<<<(EE + 255) / 256, 256>>>(ei);

    dim3 g1((NN + 63) / 64, HID / 64);
    k_gemm1<<<g1, 256>>>(x, W1, b1);
    dim3 g2((NN + 63) / 64, 1);
    k_gemm2<<<g2, 256>>>(W2, b2, coes);

    int warpsGrid = (NN * 32 + 255) / 256;
    for (int hp = 0; hp < PHOPS; hp++)
        k_spmm<<<warpsGrid, 256>>>(hp & 1, coes, hp + 1);

    k_lsm<<<warpsGrid, 256>>>((float*)d_out);
}

// round 6
// speedup vs baseline: 1.6062x; 1.6062x over previous
#include <cuda_runtime.h>
#include <cuda_bf16.h>
#include <cstdint>

#define NN   50000
#define EE   800000
#define INC  512
#define HID  256
#define OUTC 64
#define PHOPS 10

// ================= scratch (static device globals; no allocation) =================
__device__ float g_h0[(size_t)NN * HID];     // relu(x@W1+b1)
__device__ float g_hA[(size_t)NN * OUTC];    // ping
__device__ float g_hB[(size_t)NN * OUTC];    // pong
__device__ float g_hidden[(size_t)NN * OUTC];
__device__ int   g_counts[NN];
__device__ int   g_fill[NN];
__device__ int   g_colptr[NN + 1];
__device__ int   g_src[EE];
__device__ float g_w[EE];
__device__ float g_dinv[NN];
__device__ int   g_is64;                     // 1 if edge_index delivered as int64
// W1 as bf16 hi/lo mma-fragments. Entry index:
//   e = ((((nb*4+nc)*16+ch)*2+ks)*4+nt)*2+pr  (nb:2, nc:4, ch:16, ks:2, nt:4, pr:2)
// g_Wfrag[e*32 + lane] = uint2{b0, b1} for mma.m16n8k16 B fragment (col layout).
__device__ uint2 g_Wfrag[2048 * 32];

__device__ __forceinline__ uint32_t smem_u32(const void* p) {
    uint32_t a;
    asm("{ .reg .u64 t; cvta.to.shared.u64 t, %1; cvt.u32.u64 %0, t; }" : "=r"(a) : "l"(p));
    return a;
}
__device__ __forceinline__ uint32_t pack_bf2(float x, float y) {
    __nv_bfloat162 h = __floats2bfloat162_rn(x, y);
    return *(uint32_t*)&h;
}

// ================= dtype detection =================
__global__ void k_detect(const void* __restrict__ ei) {
    if (blockIdx.x == 0 && threadIdx.x == 0) {
        const long long* e64 = (const long long*)ei;
        int ok = 1;
#pragma unroll
        for (int i = 0; i < 16; i++) {
            long long v = e64[i];
            if (v < 0 || v >= NN) ok = 0;
        }
        g_is64 = ok;
    }
}

__device__ __forceinline__ void load_edge(const void* __restrict__ ei, int i, int& r, int& c) {
    if (g_is64) {
        r = (int)((const long long*)ei)[i];
        c = (int)((const long long*)ei)[EE + i];
    } else {
        r = ((const int*)ei)[i];
        c = ((const int*)ei)[EE + i];
    }
}

// ================= preprocessing =================
__global__ void k_zero() {
    int i = blockIdx.x * blockDim.x + threadIdx.x;
    if (i < NN) { g_counts[i] = 0; g_fill[i] = 0; }
}

__global__ void k_hist(const void* __restrict__ ei) {
    int i = blockIdx.x * blockDim.x + threadIdx.x;
    if (i < EE) {
        int r, c;
        load_edge(ei, i, r, c);
        if ((unsigned)c < NN) atomicAdd(&g_counts[c], 1);
    }
}

__global__ void k_dinv() {
    int i = blockIdx.x * blockDim.x + threadIdx.x;
    if (i < NN) g_dinv[i] = rsqrtf((float)(g_counts[i] + 1)); // +1 self loop
}

// warp-shuffle exclusive scan of g_counts -> g_colptr (1 block of 1024)
__global__ void k_scan() {
    __shared__ int wsum[32];
    __shared__ int chunk_base;
    int tid = threadIdx.x;
    int lane = tid & 31, wid = tid >> 5;
    if (tid == 0) chunk_base = 0;
    __syncthreads();
    for (int base = 0; base < NN; base += 1024) {
        int i = base + tid;
        int v = (i < NN) ? g_counts[i] : 0;
        int incl = v;
#pragma unroll
        for (int o = 1; o < 32; o <<= 1) {
            int t = __shfl_up_sync(0xffffffffu, incl, o);
            if (lane >= o) incl += t;
        }
        if (lane == 31) wsum[wid] = incl;
        __syncthreads();
        if (wid == 0) {
            int s = wsum[lane];
            int si = s;
#pragma unroll
            for (int o = 1; o < 32; o <<= 1) {
                int t = __shfl_up_sync(0xffffffffu, si, o);
                if (lane >= o) si += t;
            }
            wsum[lane] = si - s;  // exclusive warp offset
        }
        __syncthreads();
        int excl = chunk_base + wsum[wid] + incl - v;
        if (i < NN) g_colptr[i] = excl;
        __syncthreads();
        if (tid == 1023) chunk_base = excl + v;
        __syncthreads();
    }
    if (tid == 0) g_colptr[NN] = chunk_base;
}

__global__ void k_scatter(const void* __restrict__ ei) {
    int i = blockIdx.x * blockDim.x + threadIdx.x;
    if (i < EE) {
        int r, c;
        load_edge(ei, i, r, c);
        if ((unsigned)r >= NN || (unsigned)c >= NN) return;
        int pos = g_colptr[c] + atomicAdd(&g_fill[c], 1);
        if ((unsigned)pos < EE) {
            g_src[pos] = r;
            g_w[pos]   = g_dinv[r] * g_dinv[c];
        }
    }
}

// ================= W1 -> bf16 hi/lo mma fragments =================
// One thread per (entry, lane): 65536 threads total.
__global__ void k_wprep(const float* __restrict__ W1) {
    int t = blockIdx.x * blockDim.x + threadIdx.x;
    if (t >= 2048 * 32) return;
    int lane = t & 31;
    int e = t >> 5;
    int pr = e & 1;
    int nt = (e >> 1) & 3;
    int ks = (e >> 3) & 1;
    int ch = (e >> 4) & 15;
    int nc = (e >> 8) & 3;
    int nb = (e >> 10) & 1;
    int n  = nb * 128 + nc * 32 + nt * 8 + (lane >> 2);
    int k0 = ch * 32 + ks * 16 + (lane & 3) * 2;
    float w00 = W1[(size_t)k0 * HID + n];
    float w01 = W1[(size_t)(k0 + 1) * HID + n];
    float w10 = W1[(size_t)(k0 + 8) * HID + n];
    float w11 = W1[(size_t)(k0 + 9) * HID + n];
    uint2 out;
    if (pr == 0) {
        out.x = pack_bf2(w00, w01);
        out.y = pack_bf2(w10, w11);
    } else {
        float l00 = w00 - __bfloat162float(__float2bfloat16(w00));
        float l01 = w01 - __bfloat162float(__float2bfloat16(w01));
        float l10 = w10 - __bfloat162float(__float2bfloat16(w10));
        float l11 = w11 - __bfloat162float(__float2bfloat16(w11));
        out.x = pack_bf2(l00, l01);
        out.y = pack_bf2(l10, l11);
    }
    g_Wfrag[e * 32 + lane] = out;
}

// ================= GEMM1 via mma.sync bf16 (hi/lo 3-pass) =================
// CTA 256 thr = 8 warps (2m x 4n). Tile 128m x 128n, K chunks of 32. grid.y=2 covers HID=256.
// A smem: bf16, padded row stride 40 halves (80B) -> conflict-free ldmatrix.
__device__ __forceinline__ void mma16816(float* d, const uint32_t* a, const uint2 b) {
    asm volatile(
        "mma.sync.aligned.m16n8k16.row.col.f32.bf16.bf16.f32 "
        "{%0,%1,%2,%3}, {%4,%5,%6,%7}, {%8,%9}, {%0,%1,%2,%3};"
        : "+f"(d[0]), "+f"(d[1]), "+f"(d[2]), "+f"(d[3])
        : "r"(a[0]), "r"(a[1]), "r"(a[2]), "r"(a[3]), "r"(b.x), "r"(b.y));
}
#define LDSM4(r, addr) \
    asm volatile("ldmatrix.sync.aligned.m8n8.x4.shared.b16 {%0,%1,%2,%3}, [%4];" \
                 : "=r"((r)[0]), "=r"((r)[1]), "=r"((r)[2]), "=r"((r)[3]) : "r"(addr))

__global__ void k_gemm1_mma(const float* __restrict__ X, const float* __restrict__ b1) {
    __shared__ __align__(16) uint32_t AsH[128 * 20];  // 128 rows x 40 halves
    __shared__ __align__(16) uint32_t AsL[128 * 20];
    int tid  = threadIdx.x;
    int wid  = tid >> 5, lane = tid & 31;
    int wm0  = (wid >> 2) * 64;        // warp m offset (0 or 64)
    int nc   = wid & 3;                // warp n column (0..3)
    int m0   = blockIdx.x * 128;
    int nb   = blockIdx.y;

    float acc[4][4][4];
#pragma unroll
    for (int i = 0; i < 4; i++)
#pragma unroll
        for (int j = 0; j < 4; j++)
#pragma unroll
            for (int q = 0; q < 4; q++) acc[i][j][q] = 0.f;

    uint32_t asmH = smem_u32(AsH), asmL = smem_u32(AsL);
    // per-lane ldmatrix row address component: (lane&15) rows + (lane>>4)*16B
    uint32_t lrow = (uint32_t)(lane & 15) * 80u + (uint32_t)(lane >> 4) * 16u;

    for (int ch = 0; ch < 16; ch++) {
        // ---- stage A chunk 128x32 fp32 -> bf16 hi/lo (1024 float4 jobs, 4/thread) ----
        __syncthreads();
#pragma unroll
        for (int it = 0; it < 4; it++) {
            int idx = tid + it * 256;
            int row = idx >> 3, seg = idx & 7;
            int m = m0 + row;
            float4 v = make_float4(0.f, 0.f, 0.f, 0.f);
            if (m < NN) v = *(const float4*)&X[(size_t)m * INC + ch * 32 + seg * 4];
            int o = row * 20 + seg * 2;
            AsH[o]     = pack_bf2(v.x, v.y);
            AsH[o + 1] = pack_bf2(v.z, v.w);
            AsL[o]     = pack_bf2(v.x - __bfloat162float(__float2bfloat16(v.x)),
                                  v.y - __bfloat162float(__float2bfloat16(v.y)));
            AsL[o + 1] = pack_bf2(v.z - __bfloat162float(__float2bfloat16(v.z)),
                                  v.w - __bfloat162float(__float2bfloat16(v.w)));
        }
        __syncthreads();

#pragma unroll
        for (int ks = 0; ks < 2; ks++) {
            uint32_t aH[4][4], aL[4][4];
#pragma unroll
            for (int mt = 0; mt < 4; mt++) {
                uint32_t off = (uint32_t)(wm0 + mt * 16) * 80u + (uint32_t)ks * 32u + lrow;
                LDSM4(aH[mt], asmH + off);
                LDSM4(aL[mt], asmL + off);
            }
            int base = ((((nb * 4 + nc) * 16 + ch) * 2 + ks) * 4);
            uint2 bH[4], bL[4];
#pragma unroll
            for (int nt = 0; nt < 4; nt++) {
                bH[nt] = g_Wfrag[(size_t)((base + nt) * 2 + 0) * 32 + lane];
                bL[nt] = g_Wfrag[(size_t)((base + nt) * 2 + 1) * 32 + lane];
            }
#pragma unroll
            for (int mt = 0; mt < 4; mt++)
#pragma unroll
                for (int nt = 0; nt < 4; nt++) mma16816(acc[mt][nt], aH[mt], bH[nt]);
#pragma unroll
            for (int mt = 0; mt < 4; mt++)
#pragma unroll
                for (int nt = 0; nt < 4; nt++) mma16816(acc[mt][nt], aL[mt], bH[nt]);
#pragma unroll
            for (int mt = 0; mt < 4; mt++)
#pragma unroll
                for (int nt = 0; nt < 4; nt++) mma16816(acc[mt][nt], aH[mt], bL[nt]);
        }
    }

    // ---- epilogue: bias + relu, direct stores ----
#pragma unroll
    for (int mt = 0; mt < 4; mt++) {
        int r0 = m0 + wm0 + mt * 16 + (lane >> 2);
#pragma unroll
        for (int nt = 0; nt < 4; nt++) {
            int gcol = nb * 128 + nc * 32 + nt * 8 + (lane & 3) * 2;
            float bi0 = __ldg(&b1[gcol]), bi1 = __ldg(&b1[gcol + 1]);
            if (r0 < NN) {
                float2 v;
                v.x = fmaxf(acc[mt][nt][0] + bi0, 0.f);
                v.y = fmaxf(acc[mt][nt][1] + bi1, 0.f);
                *(float2*)&g_h0[(size_t)r0 * HID + gcol] = v;
            }
            int r1 = r0 + 8;
            if (r1 < NN) {
                float2 v;
                v.x = fmaxf(acc[mt][nt][2] + bi0, 0.f);
                v.y = fmaxf(acc[mt][nt][3] + bi1, 0.f);
                *(float2*)&g_h0[(size_t)r1 * HID + gcol] = v;
            }
        }
    }
}

// ================= GEMM2 (SIMT): hA = h0 @ W2 + b2; hidden = coes[0]*hA =================
__global__ void k_gemm2(const float* __restrict__ W, const float* __restrict__ b,
                        const float* __restrict__ coes) {
    __shared__ float As[16][65];
    __shared__ float Bs[16][64];
    int m0 = blockIdx.x * 64;
    int t  = threadIdx.x;
    int tm = (t >> 4) << 2;
    int tn = (t & 15) << 2;
    int arow = t >> 2, aseg = t & 3;
    int brow = t >> 4, bseg = t & 15;

    float acc[4][4];
#pragma unroll
    for (int i = 0; i < 4; i++)
#pragma unroll
        for (int j = 0; j < 4; j++) acc[i][j] = 0.f;

    for (int k0 = 0; k0 < HID; k0 += 16) {
        float4 av = make_float4(0.f, 0.f, 0.f, 0.f);
        int ar = m0 + arow;
        if (ar < NN) av = *(const float4*)&g_h0[(size_t)ar * HID + k0 + aseg * 4];
        float4 bv = *(const float4*)&W[(size_t)(k0 + brow) * OUTC + bseg * 4];
        __syncthreads();
        As[aseg * 4 + 0][arow] = av.x;
        As[aseg * 4 + 1][arow] = av.y;
        As[aseg * 4 + 2][arow] = av.z;
        As[aseg * 4 + 3][arow] = av.w;
        *(float4*)&Bs[brow][bseg * 4] = bv;
        __syncthreads();
#pragma unroll
        for (int k = 0; k < 16; k++) {
            float a[4], bb[4];
#pragma unroll
            for (int i = 0; i < 4; i++) a[i] = As[k][tm + i];
#pragma unroll
            for (int j = 0; j < 4; j++) bb[j] = Bs[k][tn + j];
#pragma unroll
            for (int i = 0; i < 4; i++)
#pragma unroll
                for (int j = 0; j < 4; j++) acc[i][j] = fmaf(a[i], bb[j], acc[i][j]);
        }
    }
    float c0 = coes[0];
#pragma unroll
    for (int i = 0; i < 4; i++) {
        int m = m0 + tm + i;
        if (m < NN) {
#pragma unroll
            for (int j = 0; j < 4; j++) {
                float v = acc[i][j] + b[tn + j];
                size_t o = (size_t)m * OUTC + tn + j;
                g_hA[o]     = v;
                g_hidden[o] = c0 * v;
            }
        }
    }
}

// ================= SpMM hop: warp per node, 64 feats = 2/lane =================
__global__ void k_spmm(int parity, const float* __restrict__ coes, int p) {
    int gid  = blockIdx.x * blockDim.x + threadIdx.x;
    int node = gid >> 5;
    int lane = gid & 31;
    if (node >= NN) return;
    const float* __restrict__ hin  = parity ? g_hB : g_hA;
    float* __restrict__       hout = parity ? g_hA : g_hB;

    int beg = g_colptr[node], end = g_colptr[node + 1];
    float a0 = 0.f, a1 = 0.f;
    for (int e = beg; e < end; e++) {
        int   s = g_src[e];
        float w = g_w[e];
        const float* hr = hin + (size_t)s * OUTC;
        a0 = fmaf(w, hr[lane],      a0);
        a1 = fmaf(w, hr[lane + 32], a1);
    }
    float d = g_dinv[node];
    float wd = d * d;
    const float* hs = hin + (size_t)node * OUTC;
    a0 = fmaf(wd, hs[lane],      a0);
    a1 = fmaf(wd, hs[lane + 32], a1);

    size_t o = (size_t)node * OUTC;
    hout[o + lane]      = a0;
    hout[o + lane + 32] = a1;
    float c = coes[p];
    g_hidden[o + lane]      += c * a0;
    g_hidden[o + lane + 32] += c * a1;
}

// ================= log_softmax over 64 feats =================
__global__ void k_lsm(float* __restrict__ out) {
    int gid  = blockIdx.x * blockDim.x + threadIdx.x;
    int node = gid >> 5;
    int lane = gid & 31;
    if (node >= NN) return;
    size_t o = (size_t)node * OUTC;
    float v0 = g_hidden[o + lane];
    float v1 = g_hidden[o + lane + 32];
    float m = fmaxf(v0, v1);
#pragma unroll
    for (int off = 16; off; off >>= 1) m = fmaxf(m, __shfl_xor_sync(0xffffffffu, m, off));
    float s = expf(v0 - m) + expf(v1 - m);
#pragma unroll
    for (int off = 16; off; off >>= 1) s += __shfl_xor_sync(0xffffffffu, s, off);
    float l = m + logf(s);
    out[o + lane]      = v0 - l;
    out[o + lane + 32] = v1 - l;
}

// ================= launch =================
extern "C" void kernel_launch(void* const* d_in, const int* in_sizes, int n_in,
                              void* d_out, int out_size) {
    const float* x    = (const float*)d_in[0];
    const void*  ei   = d_in[1];                // int32 or int64: detected on device
    const float* W1   = (const float*)d_in[2];
    const float* b1   = (const float*)d_in[3];
    const float* W2   = (const float*)d_in[4];
    const float* b2   = (const float*)d_in[5];
    const float* coes = (const float*)d_in[6];
    (void)in_sizes; (void)n_in; (void)out_size;

    k_detect<<<1, 32>>>(ei);
    k_zero<<<(NN + 255) / 256, 256>>>();
    k_hist<<<(EE + 255) / 256, 256>>>(ei);
    k_wprep<<<(2048 * 32 + 255) / 256, 256>>>(W1);
    k_dinv<<<(NN + 255) / 256, 256>>>();
    k_scan<<<1, 1024>>>();
    k_scatter<<<(EE + 255) / 256, 256>>>(ei);

    dim3 g1((NN + 127) / 128, 2);
    k_gemm1_mma<<<g1, 256>>>(x, b1);
    k_gemm2<<<(NN + 63) / 64, 256>>>(W2, b2, coes);

    int warpsGrid = (NN * 32 + 255) / 256;
    for (int hp = 0; hp < PHOPS; hp++)
        k_spmm<<<warpsGrid, 256>>>(hp & 1, coes, hp + 1);

    k_lsm<<<warpsGrid, 256>>>((float*)d_out);
}